// round 3
// baseline (speedup 1.0000x reference)
#include <cuda_runtime.h>
#include <cuda_bf16.h>

#define N_NODES 50000
#define N_EDGES 800000
#define NUM_GRAPHS 256
#define D 64
#define EPS 1e-5f

// ---------------- scratch (device globals; no allocation) ----------------
__device__ float g_xw[N_NODES * D];    // x @ W  (per layer)
__device__ float g_agg[N_NODES * D];   // scatter accumulator / hidden state
__device__ float g_deg[N_NODES];
__device__ float g_dinv[N_NODES];
__device__ float g_pooled[NUM_GRAPHS * D];
__device__ float g_cnt[NUM_GRAPHS];

// ---------------- small utility kernels ----------------
__global__ void k_deg_init() {
    int i = blockIdx.x * blockDim.x + threadIdx.x;
    if (i < N_NODES) g_deg[i] = 1.0f;  // self-loop
}

__global__ void k_deg_count(const int* __restrict__ col) {
    int e = blockIdx.x * blockDim.x + threadIdx.x;
    if (e < N_EDGES) atomicAdd(&g_deg[col[e]], 1.0f);
}

__global__ void k_dinv() {
    int i = blockIdx.x * blockDim.x + threadIdx.x;
    if (i < N_NODES) g_dinv[i] = rsqrtf(g_deg[i]);
}

__global__ void k_zero_agg() {
    int i = blockIdx.x * blockDim.x + threadIdx.x;
    if (i < N_NODES * D) g_agg[i] = 0.0f;
}

__global__ void k_zero_pool() {
    int i = blockIdx.x * blockDim.x + threadIdx.x;
    if (i < NUM_GRAPHS * D) g_pooled[i] = 0.0f;
    if (i < NUM_GRAPHS) g_cnt[i] = 0.0f;
}

// ---------------- GEMM: C[n,64] = A[n,64] @ W[64,64] ----------------
__global__ void k_gemm64(const float* __restrict__ A,
                         const float* __restrict__ W,
                         float* __restrict__ C) {
    __shared__ float Ws[64][65];
    __shared__ float As[64][65];
    int row0 = blockIdx.x * 64;
    int tid = threadIdx.x;
    #pragma unroll
    for (int i = tid; i < 4096; i += 256) {
        Ws[i >> 6][i & 63] = W[i];
        int r = i >> 6, c = i & 63;
        As[r][c] = (row0 + r < N_NODES) ? A[(row0 + r) * D + c] : 0.0f;
    }
    __syncthreads();
    #pragma unroll
    for (int t = 0; t < 16; t++) {
        int idx = t * 256 + tid;
        int r = idx >> 6, c = idx & 63;
        float acc = 0.0f;
        #pragma unroll
        for (int k = 0; k < 64; k++) acc = fmaf(As[r][k], Ws[k][c], acc);
        if (row0 + r < N_NODES) C[(row0 + r) * D + c] = acc;
    }
}

// ---------------- edge scatter: agg[col] += dinv[row]*dinv[col]*xw[row] ----------------
// one warp per edge; lane handles columns lane and lane+32.
__global__ void k_scatter(const int* __restrict__ row,
                          const int* __restrict__ col) {
    int gtid = blockIdx.x * blockDim.x + threadIdx.x;
    int e = gtid >> 5;
    int lane = gtid & 31;
    if (e >= N_EDGES) return;
    int r = row[e];
    int c = col[e];
    float s = g_dinv[r] * g_dinv[c];
    float v0 = s * g_xw[r * D + lane];
    float v1 = s * g_xw[r * D + lane + 32];
    atomicAdd(&g_agg[c * D + lane], v0);
    atomicAdd(&g_agg[c * D + lane + 32], v1);
}

// ---------------- epilogue: add self-loop + bias, BN, ReLU (in-place on g_agg) ----------------
__global__ void k_epilogue(const float* __restrict__ b,
                           const float* __restrict__ bg,
                           const float* __restrict__ bb,
                           const float* __restrict__ bm,
                           const float* __restrict__ bv) {
    int i = blockIdx.x * blockDim.x + threadIdx.x;
    if (i >= N_NODES * D) return;
    int node = i >> 6, j = i & 63;
    float di = g_dinv[node];
    float val = g_agg[i] + di * di * g_xw[i] + b[j];
    val = (val - bm[j]) * rsqrtf(bv[j] + EPS) * bg[j] + bb[j];
    g_agg[i] = fmaxf(val, 0.0f);
}

// ---------------- global mean pool (sum + count via atomics) ----------------
__global__ void k_pool(const int* __restrict__ batch) {
    int i = blockIdx.x * blockDim.x + threadIdx.x;
    if (i >= N_NODES * D) return;
    int node = i >> 6, j = i & 63;
    int g = batch[node];
    atomicAdd(&g_pooled[g * D + j], g_agg[i]);
    if (j == 0) atomicAdd(&g_cnt[g], 1.0f);
}

// ---------------- MLP head: one block per graph ----------------
__global__ void k_mlp(const float* __restrict__ hW1, const float* __restrict__ hb1,
                      const float* __restrict__ hg1, const float* __restrict__ hbb1,
                      const float* __restrict__ hm1, const float* __restrict__ hv1,
                      const float* __restrict__ hW2, const float* __restrict__ hb2,
                      const float* __restrict__ hg2, const float* __restrict__ hbb2,
                      const float* __restrict__ hm2, const float* __restrict__ hv2,
                      const float* __restrict__ hW3, const float* __restrict__ hb3,
                      const float* __restrict__ hW4, const float* __restrict__ hb4,
                      float* __restrict__ out) {
    __shared__ float p[64];
    __shared__ float z1[256];
    __shared__ float z2[128];
    __shared__ float z3[64];
    int g = blockIdx.x;
    int tid = threadIdx.x;
    if (tid < 64) {
        float c = fmaxf(g_cnt[g], 1.0f);
        p[tid] = g_pooled[g * D + tid] / c;
    }
    __syncthreads();
    // layer 1: 64 -> 256, BN, ReLU
    {
        float acc = hb1[tid];
        #pragma unroll
        for (int k = 0; k < 64; k++) acc = fmaf(p[k], hW1[k * 256 + tid], acc);
        acc = (acc - hm1[tid]) * rsqrtf(hv1[tid] + EPS) * hg1[tid] + hbb1[tid];
        z1[tid] = fmaxf(acc, 0.0f);
    }
    __syncthreads();
    // layer 2: 256 -> 128, BN, ReLU
    if (tid < 128) {
        float acc = hb2[tid];
        #pragma unroll 8
        for (int k = 0; k < 256; k++) acc = fmaf(z1[k], hW2[k * 128 + tid], acc);
        acc = (acc - hm2[tid]) * rsqrtf(hv2[tid] + EPS) * hg2[tid] + hbb2[tid];
        z2[tid] = fmaxf(acc, 0.0f);
    }
    __syncthreads();
    // layer 3: 128 -> 64, ReLU
    if (tid < 64) {
        float acc = hb3[tid];
        #pragma unroll 8
        for (int k = 0; k < 128; k++) acc = fmaf(z2[k], hW3[k * 64 + tid], acc);
        z3[tid] = fmaxf(acc, 0.0f);
    }
    __syncthreads();
    // layer 4: 64 -> 1
    if (tid == 0) {
        float acc = hb4[0];
        #pragma unroll
        for (int k = 0; k < 64; k++) acc = fmaf(z3[k], hW4[k], acc);
        out[g] = acc;
    }
}

// ---------------- launch ----------------
extern "C" void kernel_launch(void* const* d_in, const int* in_sizes, int n_in,
                              void* d_out, int out_size) {
    const float* x      = (const float*)d_in[0];
    const int*   ei     = (const int*)d_in[1];    // [2, E] int32 (JAX x64 disabled)
    const int*   batch  = (const int*)d_in[2];    // [N] int32
    const float* gcn_W0 = (const float*)d_in[3];
    const float* gcn_b0 = (const float*)d_in[4];
    const float* bn_g0  = (const float*)d_in[5];
    const float* bn_b0  = (const float*)d_in[6];
    const float* bn_m0  = (const float*)d_in[7];
    const float* bn_v0  = (const float*)d_in[8];
    const float* gcn_W1 = (const float*)d_in[9];
    const float* gcn_b1 = (const float*)d_in[10];
    const float* bn_g1  = (const float*)d_in[11];
    const float* bn_b1  = (const float*)d_in[12];
    const float* bn_m1  = (const float*)d_in[13];
    const float* bn_v1  = (const float*)d_in[14];
    const float* hW1 = (const float*)d_in[15];
    const float* hb1 = (const float*)d_in[16];
    const float* hg1 = (const float*)d_in[17];
    const float* hbb1= (const float*)d_in[18];
    const float* hm1 = (const float*)d_in[19];
    const float* hv1 = (const float*)d_in[20];
    const float* hW2 = (const float*)d_in[21];
    const float* hb2 = (const float*)d_in[22];
    const float* hg2 = (const float*)d_in[23];
    const float* hbb2= (const float*)d_in[24];
    const float* hm2 = (const float*)d_in[25];
    const float* hv2 = (const float*)d_in[26];
    const float* hW3 = (const float*)d_in[27];
    const float* hb3 = (const float*)d_in[28];
    const float* hW4 = (const float*)d_in[29];
    const float* hb4 = (const float*)d_in[30];
    float* out = (float*)d_out;

    const int* erow = ei;             // source
    const int* ecol = ei + N_EDGES;   // target

    // Resolve device addresses of __device__ scratch (host shadow symbol is
    // not a device pointer).
    float *p_xw = nullptr, *p_agg = nullptr;
    cudaGetSymbolAddress((void**)&p_xw, g_xw);
    cudaGetSymbolAddress((void**)&p_agg, g_agg);

    const int T = 256;
    int gN   = (N_NODES + T - 1) / T;
    int gE   = (N_EDGES + T - 1) / T;
    int gND  = (N_NODES * D + T - 1) / T;
    int gRows = (N_NODES + 63) / 64;
    int gScat = (int)(((long long)N_EDGES * 32 + T - 1) / T);

    // degree / dinv
    k_deg_init<<<gN, T>>>();
    k_deg_count<<<gE, T>>>(ecol);
    k_dinv<<<gN, T>>>();

    // GCN layer 0
    k_gemm64<<<gRows, T>>>(x, gcn_W0, p_xw);
    k_zero_agg<<<gND, T>>>();
    k_scatter<<<gScat, T>>>(erow, ecol);
    k_epilogue<<<gND, T>>>(gcn_b0, bn_g0, bn_b0, bn_m0, bn_v0);

    // GCN layer 1 (input = g_agg, gemm writes g_xw, scatter back into g_agg)
    k_gemm64<<<gRows, T>>>(p_agg, gcn_W1, p_xw);
    k_zero_agg<<<gND, T>>>();
    k_scatter<<<gScat, T>>>(erow, ecol);
    k_epilogue<<<gND, T>>>(gcn_b1, bn_g1, bn_b1, bn_m1, bn_v1);

    // pool
    k_zero_pool<<<(NUM_GRAPHS * D + T - 1) / T, T>>>();
    k_pool<<<gND, T>>>(batch);

    // MLP head
    k_mlp<<<NUM_GRAPHS, 256>>>(hW1, hb1, hg1, hbb1, hm1, hv1,
                               hW2, hb2, hg2, hbb2, hm2, hv2,
                               hW3, hb3, hW4, hb4, out);
}